// round 9
// baseline (speedup 1.0000x reference)
#include <cuda_runtime.h>
#include <cuda_bf16.h>
#include <cuda_fp16.h>
#include <cuda_fp8.h>
#include <cstdint>

#define BB 64
#define TT 512
#define SS 4
#define HH 512
#define VV 10000
#define HALFH 256

// ---------------- device scratch ----------------
__device__ float g_lse[SS * HH];
__device__ float g_leT[(size_t)SS * VV * HH];          // [s][v][h]
__device__ float g_E[(size_t)BB * TT * HH];            // exp(em - smax)
__device__ float g_smax[BB * TT];
__device__ unsigned char g_P8[HH * HH];                // e4m3(P*256), row-major [j][k]
__device__ unsigned char g_P8F[2 * 131072];            // per-rank chunked k-major [r][c][k][16]
__device__ float g_corr[HH];                           // per-row quant row-sum correction
__device__ int g_is64;

// ---------------- helpers ----------------
__device__ __forceinline__ float warp_sum(float v) {
    #pragma unroll
    for (int o = 16; o; o >>= 1) v += __shfl_xor_sync(0xffffffffu, v, o);
    return v;
}
__device__ __forceinline__ float warp_max(float v) {
    #pragma unroll
    for (int o = 16; o; o >>= 1) v = fmaxf(v, __shfl_xor_sync(0xffffffffu, v, o));
    return v;
}
__device__ __forceinline__ uint32_t smem_u32(const void* p) {
    uint32_t a;
    asm("{ .reg .u64 t; cvta.to.shared.u64 t, %1; cvt.u32.u64 %0, t; }" : "=r"(a) : "l"(p));
    return a;
}
__device__ __forceinline__ __half2 u32_h2(unsigned u) {
    __half2 h;
    *reinterpret_cast<unsigned*>(&h) = u;
    return h;
}
// sign-free e4m3 -> half via bit shift: half_bits = byte<<7, value = e4m3 * 2^-8 EXACTLY
// (incl. subnormals). P stored as e4m3(P*256) => dequant = ~P (corr fixes row sums).
__device__ __forceinline__ __half2 fp8lo(unsigned q) { return u32_h2((q & 0x00ff00ffu) << 7); }   // (b0,b2)
__device__ __forceinline__ __half2 fp8hi(unsigned q) { return u32_h2((q >> 1) & 0x7f807f80u); }   // (b1,b3)

__device__ __forceinline__ void mbar_init(uint32_t m, unsigned cnt) {
    asm volatile("mbarrier.init.shared.b64 [%0], %1;" :: "r"(m), "r"(cnt) : "memory");
}
__device__ __forceinline__ void mbar_arrive_remote(uint32_t m_local, unsigned peer) {
    asm volatile("{\n\t.reg .b32 r;\n\t"
                 "mapa.shared::cluster.u32 r, %0, %1;\n\t"
                 "mbarrier.arrive.release.cluster.shared::cluster.b64 _, [r];\n\t}"
                 :: "r"(m_local), "r"(peer) : "memory");
}
__device__ __forceinline__ void st_remote_f32(uint32_t a_local, unsigned peer, float v) {
    asm volatile("{\n\t.reg .b32 r;\n\t"
                 "mapa.shared::cluster.u32 r, %0, %1;\n\t"
                 "st.shared::cluster.f32 [r], %2;\n\t}"
                 :: "r"(a_local), "r"(peer), "f"(v) : "memory");
}
__device__ __forceinline__ void mbar_wait(uint32_t m, unsigned parity) {
    asm volatile("{\n\t.reg .pred P;\n\t"
                 "WL_%=:\n\t"
                 "mbarrier.try_wait.parity.acquire.cluster.shared::cta.b64 P, [%0], %1, 0x989680;\n\t"
                 "@P bra WD_%=;\n\t"
                 "bra WL_%=;\n\t"
                 "WD_%=:\n\t}"
                 :: "r"(m), "r"(parity) : "memory");
}
#define CLUSTER_SYNC_() do { \
    asm volatile("barrier.cluster.arrive.aligned;" ::: "memory"); \
    asm volatile("barrier.cluster.wait.aligned;" ::: "memory"); } while (0)

// ---------------- kernel 0: detect int64 vs int32 ----------------
__global__ void detect_kernel(const int* obs32) {
    if (threadIdx.x == 0) {
        int f = 1;
        for (int i = 0; i < 128; ++i)
            if (obs32[2 * i + 1] != 0) { f = 0; break; }
        g_is64 = f;
    }
}

// ---------------- kernel 1: lse over V ----------------
__global__ void lse_kernel(const float* __restrict__ emis) {
    int row = blockIdx.x;
    const float4* x4 = (const float4*)(emis + (size_t)row * VV);
    int tid = threadIdx.x;
    __shared__ float sr[256];

    float m = -1e30f;
    for (int i = tid; i < VV / 4; i += 256) {
        float4 v = x4[i];
        m = fmaxf(m, fmaxf(fmaxf(v.x, v.y), fmaxf(v.z, v.w)));
    }
    sr[tid] = m; __syncthreads();
    for (int s = 128; s; s >>= 1) { if (tid < s) sr[tid] = fmaxf(sr[tid], sr[tid + s]); __syncthreads(); }
    m = sr[0]; __syncthreads();

    float sum = 0.f;
    for (int i = tid; i < VV / 4; i += 256) {
        float4 v = x4[i];
        sum += expf(v.x - m) + expf(v.y - m) + expf(v.z - m) + expf(v.w - m);
    }
    sr[tid] = sum; __syncthreads();
    for (int s = 128; s; s >>= 1) { if (tid < s) sr[tid] += sr[tid + s]; __syncthreads(); }
    if (tid == 0) g_lse[row] = m + logf(sr[0]);
}

// ---------------- kernel 2: transpose with lse subtract ----------------
__global__ void transpose_kernel(const float* __restrict__ emis) {
    __shared__ float tile[32][33];
    int s  = blockIdx.z;
    int v0 = blockIdx.x * 32;
    int h0 = blockIdx.y * 32;
    int tx = threadIdx.x, ty = threadIdx.y;

    #pragma unroll
    for (int r = 0; r < 4; ++r) {
        int h = h0 + ty + 8 * r;
        int v = v0 + tx;
        float val = 0.f;
        if (v < VV) val = emis[((size_t)s * HH + h) * VV + v] - g_lse[s * HH + h];
        tile[ty + 8 * r][tx] = val;
    }
    __syncthreads();
    #pragma unroll
    for (int r = 0; r < 4; ++r) {
        int v = v0 + ty + 8 * r;
        int h = h0 + tx;
        if (v < VV) g_leT[((size_t)s * VV + v) * HH + h] = tile[tx][ty + 8 * r];
    }
}

// ---------------- kernel 3: P8 = e4m3(softmax(tran)*256) + row-sum corr ----------------
__global__ void psoftmax_kernel(const float* __restrict__ tran) {
    int j = blockIdx.x;
    const float* row = tran + (size_t)j * HH;
    int tid = threadIdx.x;
    __shared__ float sr[256];

    float a = row[tid], b = row[tid + 256];
    sr[tid] = fmaxf(a, b); __syncthreads();
    for (int s = 128; s; s >>= 1) { if (tid < s) sr[tid] = fmaxf(sr[tid], sr[tid + s]); __syncthreads(); }
    float m = sr[0]; __syncthreads();

    float ea = expf(a - m), eb = expf(b - m);
    sr[tid] = ea + eb; __syncthreads();
    for (int s = 128; s; s >>= 1) { if (tid < s) sr[tid] += sr[tid + s]; __syncthreads(); }
    float inv = 256.0f / sr[0];
    __syncthreads();

    __nv_fp8_storage_t qa = __nv_cvt_float_to_fp8(ea * inv, __NV_SATFINITE, __NV_E4M3);
    __nv_fp8_storage_t qb = __nv_cvt_float_to_fp8(eb * inv, __NV_SATFINITE, __NV_E4M3);
    g_P8[(size_t)j * HH + tid]       = qa;
    g_P8[(size_t)j * HH + tid + 256] = qb;

    __half_raw ha = __nv_cvt_fp8_to_halfraw(qa, __NV_E4M3);
    __half_raw hb = __nv_cvt_fp8_to_halfraw(qb, __NV_E4M3);
    float da = __half2float(*(__half*)&ha) + __half2float(*(__half*)&hb);
    sr[tid] = da; __syncthreads();
    for (int s = 128; s; s >>= 1) { if (tid < s) sr[tid] += sr[tid + s]; __syncthreads(); }
    if (tid == 0) g_corr[j] = 256.0f / sr[0];
}

// ---------------- kernel 3b: chunk-interleaved k-major repack ----------------
// g_P8F[r][c*8192 + k*16 + d] = g_P8[(r*256 + c*16 + d)][k]
__global__ void ptrans_kernel() {
    __shared__ unsigned char stage[16 * 516];
    int cc = blockIdx.x;          // chunk 0..15
    int r  = blockIdx.y;          // rank 0..1
    int tid = threadIdx.x;

    for (int idx = tid; idx < 16 * 512; idx += 512) {
        int d = idx >> 9, kk = idx & 511;
        stage[d * 516 + kk] = g_P8[(size_t)(r * 256 + cc * 16 + d) * 512 + kk];
    }
    __syncthreads();
    for (int idx = tid; idx < 16 * 512; idx += 512) {
        int kk = idx >> 4, d = idx & 15;
        g_P8F[(size_t)r * 131072 + cc * 8192 + idx] = stage[d * 516 + kk];
    }
}

// ---------------- kernel 4: gather em, smax & E ----------------
__global__ void emE_kernel(const void* __restrict__ obs_raw,
                           const float* __restrict__ priors) {
    int t = blockIdx.x, b = blockIdx.y;
    int tid = threadIdx.x;
    int lane = tid & 31, wid = tid >> 5;
    __shared__ float sm[4];

    int o[SS];
    if (g_is64) {
        const long long* p = (const long long*)obs_raw + ((size_t)(b * TT + t)) * SS;
        #pragma unroll
        for (int s = 0; s < SS; ++s) o[s] = (int)p[s];
    } else {
        const int* p = (const int*)obs_raw + ((size_t)(b * TT + t)) * SS;
        #pragma unroll
        for (int s = 0; s < SS; ++s) o[s] = p[s];
    }

    float4 acc = make_float4(0.f, 0.f, 0.f, 0.f);
    #pragma unroll
    for (int s = 0; s < SS; ++s) {
        const float4* r = (const float4*)(g_leT + ((size_t)s * VV + o[s]) * HH);
        float4 v = r[tid];
        acc.x += v.x; acc.y += v.y; acc.z += v.z; acc.w += v.w;
    }
    acc.x *= 0.25f; acc.y *= 0.25f; acc.z *= 0.25f; acc.w *= 0.25f;

    if (t == 0) {
        float4 pr = ((const float4*)priors)[tid];
        acc.x += pr.x; acc.y += pr.y; acc.z += pr.z; acc.w += pr.w;
    }

    float m = fmaxf(fmaxf(acc.x, acc.y), fmaxf(acc.z, acc.w));
    m = warp_max(m);
    if (lane == 0) sm[wid] = m;
    __syncthreads();
    m = fmaxf(fmaxf(sm[0], sm[1]), fmaxf(sm[2], sm[3]));

    float4 e;
    e.x = __expf(acc.x - m); e.y = __expf(acc.y - m);
    e.z = __expf(acc.z - m); e.w = __expf(acc.w - m);
    ((float4*)(g_E + ((size_t)(b * TT + t)) * HH))[tid] = e;
    if (tid == 0) g_smax[b * TT + t] = m;
}

// ---------------- kernel 5: forward, row-split cluster, k-per-thread matvec ----------------
// CTA r owns P rows j in [r*256, +256). Thread k (=tid, global) accumulates tot_k
// over ALL own j in registers -> no cross-warp partial reduction.
// Non-own threads ship tot immediately; own threads combine with stale cross-half
// ratio R (R8-verified math). One __syncthreads + one bar.sync per step.
// smem layout (bytes)
#define SM_P     0            // 16 chunks x 512 k x 16B = 131072
#define SM_PH    131072       // 128 u32 (swizzled half pairs of p) = 512
#define SM_RECV  131584       // 2 x 256 f32 (peer partials) = 2048
#define SM_RED   133632       // 8 f32 = 32
#define SM_HP    133664       // 2 f32 (peer H, double buffered)
#define SM_HPF   133672       // 1 f32 (peer final H)
#define SM_MBAR  133680       // 8B (257 arrivals)
#define SM_MBARF 133688       // 8B (1 arrival)
#define SMEM_TOTAL 133696

__global__ void __launch_bounds__(512, 1) __cluster_dims__(2, 1, 1)
forward_kernel(const void* __restrict__ lengths_raw, float* __restrict__ out) {
    extern __shared__ char sm[];
    const int tid  = threadIdx.x;          // global k = tid
    const int b    = blockIdx.x >> 1;
    const unsigned rank = blockIdx.x & 1;
    const unsigned peer = rank ^ 1;
    const int lane = tid & 31, wid = tid >> 5;
    const bool own = ((unsigned)(wid >> 3) == rank);    // k in own half
    const bool leader = (tid == (int)(rank << 8));
    const int u = tid & 255;

    const uint32_t sbase = smem_u32(sm);
    const uint32_t mbarV = sbase + SM_MBAR;
    const uint32_t mbarF = sbase + SM_MBARF;
    float* recv = (float*)(sm + SM_RECV);
    float* red  = (float*)(sm + SM_RED);
    float* hps  = (float*)(sm + SM_HP);
    float* hpf  = (float*)(sm + SM_HPF);

    if (tid == 0) { mbar_init(mbarV, 257); mbar_init(mbarF, 1); }

    // load chunk-interleaved k-major P slice (own 256 j-rows), coalesced
    {
        const uint4* src = (const uint4*)(g_P8F + (size_t)rank * 131072);
        uint4* dst = (uint4*)(sm + SM_P);
        #pragma unroll
        for (int r = 0; r < 16; ++r) dst[tid + 512 * r] = src[tid + 512 * r];
    }
    const float corrk = g_corr[tid];
    __syncthreads();
    CLUSTER_SYNC_();

    const int len = g_is64 ? (int)((const long long*)lengths_raw)[b]
                           : ((const int*)lengths_raw)[b];
    const float* Eb  = g_E + (size_t)b * TT * HH;
    const float* smx = g_smax + (size_t)b * TT;

    unsigned pp = 0;
    float c = 0.f, run = 0.f;
    float R = 1.f;            // cross-half scale ratio (stale by 1 step; stable)
    float Ho = 1.f;           // own half-sum (register)

    float e_cur = own ? __ldg(Eb + tid) : 0.f;
    float smt_cur = leader ? __ldg(smx) : 0.f;

    const char* Pc = sm + SM_P;
    const char* PH = sm + SM_PH;

    for (int t = 0; t < len; ++t) {
        const int bufW = t & 1, bufR = bufW ^ 1;

        float e_next = 0.f, smt_next = 0.f;
        if (t + 1 < len) {
            if (own) e_next = __ldg(Eb + (size_t)(t + 1) * HH + tid);
            if (leader) smt_next = __ldg(smx + t + 1);
        }

        float w = 0.f;
        if (t == 0) {
            if (own) w = e_cur;
            if (own) { /* no wait at t=0 */ }
        } else {
            // matvec: thread-local accumulation over all 256 own j's for k=tid
            __half2 a0 = __float2half2_rn(0.f), a1 = a0, a2 = a0, a3 = a0;
            #pragma unroll
            for (int c16 = 0; c16 < 16; ++c16) {
                uint4 q  = *(const uint4*)(Pc + c16 * 8192 + tid * 16);
                uint4 pA = *(const uint4*)(PH + c16 * 32);
                uint4 pB = *(const uint4*)(PH + c16 * 32 + 16);
                a0 = __hfma2(u32_h2(pA.x), fp8lo(q.x), a0);
                a1 = __hfma2(u32_h2(pA.y), fp8hi(q.x), a1);
                a2 = __hfma2(u32_h2(pA.z), fp8lo(q.y), a2);
                a3 = __hfma2(u32_h2(pA.w), fp8hi(q.y), a3);
                a0 = __hfma2(u32_h2(pB.x), fp8lo(q.z), a0);
                a1 = __hfma2(u32_h2(pB.y), fp8hi(q.z), a1);
                a2 = __hfma2(u32_h2(pB.z), fp8lo(q.w), a2);
                a3 = __hfma2(u32_h2(pB.w), fp8hi(q.w), a3);
            }
            __half2 hs = __hadd2(__hadd2(a0, a1), __hadd2(a2, a3));
            float2 fs = __half22float2(hs);
            float tot = fs.x + fs.y;

            if (!own) {
                // ship peer's k immediately (thread-local tot, no barrier needed)
                st_remote_f32(sbase + SM_RECV + ((unsigned)bufW << 10) + 4u * (unsigned)u, peer, tot);
                mbar_arrive_remote(mbarV, peer);
            } else {
                // wait: peer partials (this step) + peer H_{t-1}
                mbar_wait(mbarV, pp); pp ^= 1;
                float Hp = hps[bufR];
                R = R * Hp * __frcp_rn(Ho);          // Ho still = H_{t-1}
                w = e_cur * fmaf(R, recv[bufW * 256 + u], tot);
            }
        }

        if (own) {
            float s1 = warp_sum(w);
            if (lane == 0) red[wid & 7] = s1;
            asm volatile("bar.sync 1, 256;" ::: "memory");
            float Hn = red[0] + red[1] + red[2] + red[3] + red[4] + red[5] + red[6] + red[7];

            // normalize own half by 2*Hn (current -> stable); swizzled fp16 store
            float pk = w * __frcp_rn(Hn + Hn) * corrk;
            __half hv = __float2half_rn(pk);
            int idx = (u & ~3) | ((u & 1) << 1) | ((u >> 1) & 1);  // (j,j+2)/(j+1,j+3) pairing
            ((__half*)(sm + SM_PH))[idx] = hv;
            Ho = Hn;

            if (leader) {
                if (t < len - 1) {
                    st_remote_f32(sbase + SM_HP + 4u * (unsigned)bufW, peer, Ho);
                    mbar_arrive_remote(mbarV, peer);
                } else {
                    st_remote_f32(sbase + SM_HPF, peer, Ho);
                    mbar_arrive_remote(mbarF, peer);
                }
                c += smt_cur;
                run += __logf(Ho + Ho);
            }
        }
        e_cur = e_next; smt_cur = smt_next;
        __syncthreads();
    }

    if (leader && rank == 0) {
        mbar_wait(mbarF, 0);
        // run includes log(2 Ho_L); replace with log(Ho_L + R*Hp_L)
        out[b] = c + run - __logf(Ho + Ho) + __logf(fmaf(R, hpf[0], Ho));
    }
    CLUSTER_SYNC_();
}

// ---------------- launcher ----------------
extern "C" void kernel_launch(void* const* d_in, const int* in_sizes, int n_in,
                              void* d_out, int out_size) {
    const void*  obs     = d_in[0];
    const void*  lengths = d_in[1];
    const float* emis    = (const float*)d_in[2];
    const float* tran    = (const float*)d_in[3];
    const float* priors  = (const float*)d_in[4];
    float* out = (float*)d_out;

    cudaFuncSetAttribute(forward_kernel, cudaFuncAttributeMaxDynamicSharedMemorySize, SMEM_TOTAL);

    detect_kernel<<<1, 32>>>((const int*)obs);
    lse_kernel<<<SS * HH, 256>>>(emis);
    transpose_kernel<<<dim3((VV + 31) / 32, HH / 32, SS), dim3(32, 8)>>>(emis);
    psoftmax_kernel<<<HH, 256>>>(tran);
    ptrans_kernel<<<dim3(16, 2), 512>>>();
    emE_kernel<<<dim3(TT, BB), 128>>>(obs, priors);
    forward_kernel<<<BB * 2, 512, SMEM_TOTAL>>>(lengths, out);
}

// round 10
// speedup vs baseline: 1.5428x; 1.5428x over previous
#include <cuda_runtime.h>
#include <cuda_bf16.h>
#include <cuda_fp16.h>
#include <cuda_fp8.h>
#include <cstdint>

#define BB 64
#define TT 512
#define SS 4
#define HH 512
#define VV 10000
#define HALFH 256

// ---------------- device scratch ----------------
__device__ float g_lse[SS * HH];
__device__ float g_leT[(size_t)SS * VV * HH];          // [s][v][h]
__device__ float g_E[(size_t)BB * TT * HH];            // exp(em - smax)
__device__ float g_smax[BB * TT];
__device__ unsigned char g_P8[HH * HH];                // e4m3(P*256), row-major [j][k]
__device__ float g_corr[HH];                           // per-row quant row-sum correction
__device__ int g_is64;

// ---------------- helpers ----------------
__device__ __forceinline__ float warp_sum(float v) {
    #pragma unroll
    for (int o = 16; o; o >>= 1) v += __shfl_xor_sync(0xffffffffu, v, o);
    return v;
}
__device__ __forceinline__ float warp_max(float v) {
    #pragma unroll
    for (int o = 16; o; o >>= 1) v = fmaxf(v, __shfl_xor_sync(0xffffffffu, v, o));
    return v;
}
__device__ __forceinline__ uint32_t smem_u32(const void* p) {
    uint32_t a;
    asm("{ .reg .u64 t; cvta.to.shared.u64 t, %1; cvt.u32.u64 %0, t; }" : "=r"(a) : "l"(p));
    return a;
}
__device__ __forceinline__ __half2 u32_h2(unsigned u) {
    __half2 h;
    *reinterpret_cast<unsigned*>(&h) = u;
    return h;
}
// sign-free e4m3 -> half via bit shift: half_bits = byte<<7, value = e4m3 * 2^-8 EXACTLY.
// P stored as e4m3(P*256) => dequant = ~P (corr fixes row sums).
__device__ __forceinline__ __half2 fp8lo(unsigned q) { return u32_h2((q & 0x00ff00ffu) << 7); }   // (b0,b2)
__device__ __forceinline__ __half2 fp8hi(unsigned q) { return u32_h2((q >> 1) & 0x7f807f80u); }   // (b1,b3)

__device__ __forceinline__ void mbar_init(uint32_t m, unsigned cnt) {
    asm volatile("mbarrier.init.shared.b64 [%0], %1;" :: "r"(m), "r"(cnt) : "memory");
}
__device__ __forceinline__ void mbar_arrive_remote(uint32_t m_local, unsigned peer) {
    asm volatile("{\n\t.reg .b32 r;\n\t"
                 "mapa.shared::cluster.u32 r, %0, %1;\n\t"
                 "mbarrier.arrive.release.cluster.shared::cluster.b64 _, [r];\n\t}"
                 :: "r"(m_local), "r"(peer) : "memory");
}
__device__ __forceinline__ void st_remote_f32(uint32_t a_local, unsigned peer, float v) {
    asm volatile("{\n\t.reg .b32 r;\n\t"
                 "mapa.shared::cluster.u32 r, %0, %1;\n\t"
                 "st.shared::cluster.f32 [r], %2;\n\t}"
                 :: "r"(a_local), "r"(peer), "f"(v) : "memory");
}
__device__ __forceinline__ void mbar_wait(uint32_t m, unsigned parity) {
    asm volatile("{\n\t.reg .pred P;\n\t"
                 "WL_%=:\n\t"
                 "mbarrier.try_wait.parity.acquire.cluster.shared::cta.b64 P, [%0], %1, 0x989680;\n\t"
                 "@P bra WD_%=;\n\t"
                 "bra WL_%=;\n\t"
                 "WD_%=:\n\t}"
                 :: "r"(m), "r"(parity) : "memory");
}
#define CLUSTER_SYNC_() do { \
    asm volatile("barrier.cluster.arrive.aligned;" ::: "memory"); \
    asm volatile("barrier.cluster.wait.aligned;" ::: "memory"); } while (0)

// ---------------- kernel 0: detect int64 vs int32 ----------------
__global__ void detect_kernel(const int* obs32) {
    if (threadIdx.x == 0) {
        int f = 1;
        for (int i = 0; i < 128; ++i)
            if (obs32[2 * i + 1] != 0) { f = 0; break; }
        g_is64 = f;
    }
}

// ---------------- kernel 1: lse over V ----------------
__global__ void lse_kernel(const float* __restrict__ emis) {
    int row = blockIdx.x;
    const float4* x4 = (const float4*)(emis + (size_t)row * VV);
    int tid = threadIdx.x;
    __shared__ float sr[256];

    float m = -1e30f;
    for (int i = tid; i < VV / 4; i += 256) {
        float4 v = x4[i];
        m = fmaxf(m, fmaxf(fmaxf(v.x, v.y), fmaxf(v.z, v.w)));
    }
    sr[tid] = m; __syncthreads();
    for (int s = 128; s; s >>= 1) { if (tid < s) sr[tid] = fmaxf(sr[tid], sr[tid + s]); __syncthreads(); }
    m = sr[0]; __syncthreads();

    float sum = 0.f;
    for (int i = tid; i < VV / 4; i += 256) {
        float4 v = x4[i];
        sum += expf(v.x - m) + expf(v.y - m) + expf(v.z - m) + expf(v.w - m);
    }
    sr[tid] = sum; __syncthreads();
    for (int s = 128; s; s >>= 1) { if (tid < s) sr[tid] += sr[tid + s]; __syncthreads(); }
    if (tid == 0) g_lse[row] = m + logf(sr[0]);
}

// ---------------- kernel 2: transpose with lse subtract ----------------
__global__ void transpose_kernel(const float* __restrict__ emis) {
    __shared__ float tile[32][33];
    int s  = blockIdx.z;
    int v0 = blockIdx.x * 32;
    int h0 = blockIdx.y * 32;
    int tx = threadIdx.x, ty = threadIdx.y;

    #pragma unroll
    for (int r = 0; r < 4; ++r) {
        int h = h0 + ty + 8 * r;
        int v = v0 + tx;
        float val = 0.f;
        if (v < VV) val = emis[((size_t)s * HH + h) * VV + v] - g_lse[s * HH + h];
        tile[ty + 8 * r][tx] = val;
    }
    __syncthreads();
    #pragma unroll
    for (int r = 0; r < 4; ++r) {
        int v = v0 + ty + 8 * r;
        int h = h0 + tx;
        if (v < VV) g_leT[((size_t)s * VV + v) * HH + h] = tile[tx][ty + 8 * r];
    }
}

// ---------------- kernel 3: P8 = e4m3(softmax(tran)*256) + row-sum corr ----------------
__global__ void psoftmax_kernel(const float* __restrict__ tran) {
    int j = blockIdx.x;
    const float* row = tran + (size_t)j * HH;
    int tid = threadIdx.x;
    __shared__ float sr[256];

    float a = row[tid], b = row[tid + 256];
    sr[tid] = fmaxf(a, b); __syncthreads();
    for (int s = 128; s; s >>= 1) { if (tid < s) sr[tid] = fmaxf(sr[tid], sr[tid + s]); __syncthreads(); }
    float m = sr[0]; __syncthreads();

    float ea = expf(a - m), eb = expf(b - m);
    sr[tid] = ea + eb; __syncthreads();
    for (int s = 128; s; s >>= 1) { if (tid < s) sr[tid] += sr[tid + s]; __syncthreads(); }
    float inv = 256.0f / sr[0];
    __syncthreads();

    __nv_fp8_storage_t qa = __nv_cvt_float_to_fp8(ea * inv, __NV_SATFINITE, __NV_E4M3);
    __nv_fp8_storage_t qb = __nv_cvt_float_to_fp8(eb * inv, __NV_SATFINITE, __NV_E4M3);
    g_P8[(size_t)j * HH + tid]       = qa;
    g_P8[(size_t)j * HH + tid + 256] = qb;

    __half_raw ha = __nv_cvt_fp8_to_halfraw(qa, __NV_E4M3);
    __half_raw hb = __nv_cvt_fp8_to_halfraw(qb, __NV_E4M3);
    float da = __half2float(*(__half*)&ha) + __half2float(*(__half*)&hb);
    sr[tid] = da; __syncthreads();
    for (int s = 128; s; s >>= 1) { if (tid < s) sr[tid] += sr[tid + s]; __syncthreads(); }
    if (tid == 0) g_corr[j] = 256.0f / sr[0];
}

// ---------------- kernel 4: gather em, smax & E ----------------
__global__ void emE_kernel(const void* __restrict__ obs_raw,
                           const float* __restrict__ priors) {
    int t = blockIdx.x, b = blockIdx.y;
    int tid = threadIdx.x;
    int lane = tid & 31, wid = tid >> 5;
    __shared__ float sm[4];

    int o[SS];
    if (g_is64) {
        const long long* p = (const long long*)obs_raw + ((size_t)(b * TT + t)) * SS;
        #pragma unroll
        for (int s = 0; s < SS; ++s) o[s] = (int)p[s];
    } else {
        const int* p = (const int*)obs_raw + ((size_t)(b * TT + t)) * SS;
        #pragma unroll
        for (int s = 0; s < SS; ++s) o[s] = p[s];
    }

    float4 acc = make_float4(0.f, 0.f, 0.f, 0.f);
    #pragma unroll
    for (int s = 0; s < SS; ++s) {
        const float4* r = (const float4*)(g_leT + ((size_t)s * VV + o[s]) * HH);
        float4 v = r[tid];
        acc.x += v.x; acc.y += v.y; acc.z += v.z; acc.w += v.w;
    }
    acc.x *= 0.25f; acc.y *= 0.25f; acc.z *= 0.25f; acc.w *= 0.25f;

    if (t == 0) {
        float4 pr = ((const float4*)priors)[tid];
        acc.x += pr.x; acc.y += pr.y; acc.z += pr.z; acc.w += pr.w;
    }

    float m = fmaxf(fmaxf(acc.x, acc.y), fmaxf(acc.z, acc.w));
    m = warp_max(m);
    if (lane == 0) sm[wid] = m;
    __syncthreads();
    m = fmaxf(fmaxf(sm[0], sm[1]), fmaxf(sm[2], sm[3]));

    float4 e;
    e.x = __expf(acc.x - m); e.y = __expf(acc.y - m);
    e.z = __expf(acc.z - m); e.w = __expf(acc.w - m);
    ((float4*)(g_E + ((size_t)(b * TT + t)) * HH))[tid] = e;
    if (tid == 0) g_smax[b * TT + t] = m;
}

// ---------------- kernel 5: forward, ROW-split cluster, aggregated arrives ----------------
// Identical to R8 except: non-own warps aggregate their 32 remote stores behind
// ONE lane-0 release-arrive (transitive HB via __syncwarp). mbarV count 257 -> 9.
// smem layout (bytes)
#define SM_P     0            // 256 rows x 512 fp8 = 131072
#define SM_PART  131072       // 8 x 512 floats = 16384
#define SM_PH    147456       // 256 u32 (half2 bcast p, own j's) = 1024
#define SM_RECV  148480       // 2 x 256 floats (peer partials, double buffered) = 2048
#define SM_RED   150528       // 8 floats
#define SM_HP    150560       // 2 floats (peer H, double buffered)
#define SM_HPF   150568       // 1 float (peer final H) + pad
#define SM_MBAR  150576       // 8B (9 arrivals: 8 partial-warps + 1 H)
#define SM_MBARF 150584       // 8B (1 arrival: final H)
#define SMEM_TOTAL 150592

__global__ void __launch_bounds__(512, 1) __cluster_dims__(2, 1, 1)
forward_kernel(const void* __restrict__ lengths_raw, float* __restrict__ out) {
    extern __shared__ char sm[];
    const int tid  = threadIdx.x;
    const int b    = blockIdx.x >> 1;
    const unsigned rank = blockIdx.x & 1;
    const unsigned peer = rank ^ 1;
    const int lane = tid & 31, wid = tid >> 5;
    const bool own = ((unsigned)(tid >> 8) == rank);    // global state j = tid is mine
    const bool leader = (tid == (int)(rank << 8));
    const int u = tid & 255;

    const uint32_t sbase = smem_u32(sm);
    const uint32_t mbarV = sbase + SM_MBAR;
    const uint32_t mbarF = sbase + SM_MBARF;
    float*    part = (float*)(sm + SM_PART);
    unsigned* p_h  = (unsigned*)(sm + SM_PH);
    float*    recv = (float*)(sm + SM_RECV);
    float*    red  = (float*)(sm + SM_RED);
    float*    hps  = (float*)(sm + SM_HP);
    float*    hpf  = (float*)(sm + SM_HPF);

    if (tid == 0) { mbar_init(mbarV, 9); mbar_init(mbarF, 1); }

    // load own j-rows of P: rows [rank*256, +256), all 512 k (contiguous 128KB)
    {
        const uint4* src = (const uint4*)(g_P8 + (size_t)rank * HALFH * HH);
        uint4* dst = (uint4*)(sm + SM_P);
        #pragma unroll
        for (int r = 0; r < 16; ++r) dst[tid + 512 * r] = src[tid + 512 * r];
    }
    const float corrk = g_corr[tid];   // row-sum correction for row j = tid (own threads)
    __syncthreads();
    CLUSTER_SYNC_();

    const int len = g_is64 ? (int)((const long long*)lengths_raw)[b]
                           : ((const int*)lengths_raw)[b];
    const float* Eb  = g_E + (size_t)b * TT * HH;
    const float* smx = g_smax + (size_t)b * TT;

    unsigned pp = 0;
    float c = 0.f, run = 0.f;
    float R = 1.f;            // cross-half scale ratio (stale by 1 step; stable)
    float Ho = 1.f;           // own half-sum (register, all own threads)

    float e_cur = own ? __ldg(Eb + tid) : 0.f;
    float smt_cur = leader ? __ldg(smx) : 0.f;

    // matvec mapping: 8 groups x 64 threads; group g -> own-local j rows [g*32, g*32+32);
    // thread i owns global k = 8i..8i+7 via one LDS.64 (uint2) per j.
    const int g = tid >> 6, i = tid & 63;
    const uint2* P2  = (const uint2*)(sm + SM_P) + (size_t)(g * 32) * 64 + i;
    const uint4* ph4 = (const uint4*)(sm + SM_PH) + g * 8;
    float* prow = part + g * 512 + i * 8;

    for (int t = 0; t < len; ++t) {
        const int bufW = t & 1, bufR = bufW ^ 1;

        float e_next = 0.f, smt_next = 0.f;
        if (t + 1 < len) {
            if (own) e_next = __ldg(Eb + (size_t)(t + 1) * HH + tid);
            if (leader) smt_next = __ldg(smx + t + 1);
        }

        float w = 0.f;
        if (t == 0) {
            if (own) w = e_cur;
        } else {
            // matvec over own 256 j's (local p only)
            unsigned prs[32];
            #pragma unroll
            for (int r = 0; r < 8; ++r) *(uint4*)&prs[4 * r] = ph4[r];
            __half2 a0 = __float2half2_rn(0.f), a1 = a0, a2 = a0, a3 = a0;
            #pragma unroll
            for (int jj = 0; jj < 32; ++jj) {
                uint2 q = P2[(size_t)jj * 64];
                __half2 hp = u32_h2(prs[jj]);
                a0 = __hfma2(hp, fp8lo(q.x), a0);   // (k0,k2)
                a1 = __hfma2(hp, fp8hi(q.x), a1);   // (k1,k3)
                a2 = __hfma2(hp, fp8lo(q.y), a2);   // (k4,k6)
                a3 = __hfma2(hp, fp8hi(q.y), a3);   // (k5,k7)
            }
            float2 f0 = __half22float2(a0), f1 = __half22float2(a1);
            float2 f2 = __half22float2(a2), f3 = __half22float2(a3);
            *(float4*)prow       = make_float4(f0.x, f1.x, f0.y, f1.y);
            *(float4*)(prow + 4) = make_float4(f2.x, f3.x, f2.y, f3.y);
            __syncthreads();

            // every thread reduces 8 partials for global k = tid
            float tot = 0.f;
            #pragma unroll
            for (int r = 0; r < 8; ++r) tot += part[r * 512 + tid];

            if (!own) {
                // ship peer's k-half; ONE aggregated arrive per warp
                st_remote_f32(sbase + SM_RECV + ((unsigned)bufW << 10) + 4u * (unsigned)u, peer, tot);
                __syncwarp();
                if (lane == 0) mbar_arrive_remote(mbarV, peer);
            } else {
                // wait: peer partial-warps (this step) + peer H_{t-1}
                mbar_wait(mbarV, pp); pp ^= 1;
                float Hp = hps[bufR];                 // peer H_{t-1}
                R = R * Hp * __frcp_rn(Ho);           // Ho still holds H_{t-1}
                float v = fmaf(R, recv[bufW * 256 + u], tot);
                w = e_cur * v;
            }
        }

        if (own) {
            float s1 = warp_sum(w);
            if (lane == 0) red[wid & 7] = s1;
            asm volatile("bar.sync 1, 256;" ::: "memory");
            float Hn = red[0] + red[1] + red[2] + red[3] + red[4] + red[5] + red[6] + red[7];

            // normalize own half by 2*Hn (current -> stable); corr fixes fp8 row sums
            float pk = w * __frcp_rn(Hn + Hn) * corrk;
            unsigned hu = (unsigned)__half_as_ushort(__float2half_rn(pk));
            hu |= hu << 16;
            p_h[u] = hu;
            Ho = Hn;

            if (leader) {
                if (t < len - 1) {
                    st_remote_f32(sbase + SM_HP + 4u * (unsigned)bufW, peer, Ho);
                    mbar_arrive_remote(mbarV, peer);
                } else {
                    st_remote_f32(sbase + SM_HPF, peer, Ho);
                    mbar_arrive_remote(mbarF, peer);
                }
                c += smt_cur;
                run += __logf(Ho + Ho);
            }
        }
        e_cur = e_next; smt_cur = smt_next;
        __syncthreads();
    }

    if (leader && rank == 0) {
        mbar_wait(mbarF, 0);
        // run includes log(2 Ho_L); replace with log(Ho_L + R*Hp_L)
        out[b] = c + run - __logf(Ho + Ho) + __logf(fmaf(R, hpf[0], Ho));
    }
    CLUSTER_SYNC_();
}

// ---------------- launcher ----------------
extern "C" void kernel_launch(void* const* d_in, const int* in_sizes, int n_in,
                              void* d_out, int out_size) {
    const void*  obs     = d_in[0];
    const void*  lengths = d_in[1];
    const float* emis    = (const float*)d_in[2];
    const float* tran    = (const float*)d_in[3];
    const float* priors  = (const float*)d_in[4];
    float* out = (float*)d_out;

    cudaFuncSetAttribute(forward_kernel, cudaFuncAttributeMaxDynamicSharedMemorySize, SMEM_TOTAL);

    detect_kernel<<<1, 32>>>((const int*)obs);
    lse_kernel<<<SS * HH, 256>>>(emis);
    transpose_kernel<<<dim3((VV + 31) / 32, HH / 32, SS), dim3(32, 8)>>>(emis);
    psoftmax_kernel<<<HH, 256>>>(tran);
    emE_kernel<<<dim3(TT, BB), 128>>>(obs, priors);
    forward_kernel<<<BB * 2, 512, SMEM_TOTAL>>>(lengths, out);
}

// round 12
// speedup vs baseline: 1.6878x; 1.0940x over previous
#include <cuda_runtime.h>
#include <cuda_bf16.h>
#include <cuda_fp16.h>
#include <cuda_fp8.h>
#include <cstdint>

#define BB 64
#define TT 512
#define SS 4
#define HH 512
#define VV 10000
#define HALFH 256

// ---------------- device scratch ----------------
__device__ float g_lse[SS * HH];
__device__ float g_leT[(size_t)SS * VV * HH];          // [s][v][h]
__device__ float g_E[(size_t)BB * TT * HH];            // exp(em - smax)
__device__ float g_smax[BB * TT];
__device__ unsigned char g_P8[HH * HH];                // e5m2(P), row-major [j][k] (NO scale)
__device__ float g_corr[HH];                           // per-row quant row-sum correction
__device__ int g_is64;

// ---------------- helpers ----------------
__device__ __forceinline__ float warp_sum(float v) {
    #pragma unroll
    for (int o = 16; o; o >>= 1) v += __shfl_xor_sync(0xffffffffu, v, o);
    return v;
}
__device__ __forceinline__ float warp_max(float v) {
    #pragma unroll
    for (int o = 16; o; o >>= 1) v = fmaxf(v, __shfl_xor_sync(0xffffffffu, v, o));
    return v;
}
__device__ __forceinline__ uint32_t smem_u32(const void* p) {
    uint32_t a;
    asm("{ .reg .u64 t; cvta.to.shared.u64 t, %1; cvt.u32.u64 %0, t; }" : "=r"(a) : "l"(p));
    return a;
}
__device__ __forceinline__ __half2 u32_h2(unsigned u) {
    __half2 h;
    *reinterpret_cast<unsigned*>(&h) = u;
    return h;
}
// e5m2 IS the top byte of fp16: dequant = ONE PRMT per half2 pair, value EXACT
// (same exponent bias 15; subnormals map exactly too). P stored unscaled.
__device__ __forceinline__ __half2 e5lo(unsigned q) { return u32_h2(__byte_perm(q, 0, 0x2404)); }  // (b0,b2)
__device__ __forceinline__ __half2 e5hi(unsigned q) { return u32_h2(__byte_perm(q, 0, 0x3414)); }  // (b1,b3)

__device__ __forceinline__ void mbar_init(uint32_t m, unsigned cnt) {
    asm volatile("mbarrier.init.shared.b64 [%0], %1;" :: "r"(m), "r"(cnt) : "memory");
}
__device__ __forceinline__ void mbar_arrive_remote(uint32_t m_local, unsigned peer) {
    asm volatile("{\n\t.reg .b32 r;\n\t"
                 "mapa.shared::cluster.u32 r, %0, %1;\n\t"
                 "mbarrier.arrive.release.cluster.shared::cluster.b64 _, [r];\n\t}"
                 :: "r"(m_local), "r"(peer) : "memory");
}
__device__ __forceinline__ void st_remote_f32(uint32_t a_local, unsigned peer, float v) {
    asm volatile("{\n\t.reg .b32 r;\n\t"
                 "mapa.shared::cluster.u32 r, %0, %1;\n\t"
                 "st.shared::cluster.f32 [r], %2;\n\t}"
                 :: "r"(a_local), "r"(peer), "f"(v) : "memory");
}
__device__ __forceinline__ void mbar_wait(uint32_t m, unsigned parity) {
    asm volatile("{\n\t.reg .pred P;\n\t"
                 "WL_%=:\n\t"
                 "mbarrier.try_wait.parity.acquire.cluster.shared::cta.b64 P, [%0], %1, 0x989680;\n\t"
                 "@P bra WD_%=;\n\t"
                 "bra WL_%=;\n\t"
                 "WD_%=:\n\t}"
                 :: "r"(m), "r"(parity) : "memory");
}
#define CLUSTER_SYNC_() do { \
    asm volatile("barrier.cluster.arrive.aligned;" ::: "memory"); \
    asm volatile("barrier.cluster.wait.aligned;" ::: "memory"); } while (0)

// ---------------- kernel 0: detect int64 vs int32 ----------------
__global__ void detect_kernel(const int* obs32) {
    if (threadIdx.x == 0) {
        int f = 1;
        for (int i = 0; i < 128; ++i)
            if (obs32[2 * i + 1] != 0) { f = 0; break; }
        g_is64 = f;
    }
}

// ---------------- kernel 1: lse over V ----------------
__global__ void lse_kernel(const float* __restrict__ emis) {
    int row = blockIdx.x;
    const float4* x4 = (const float4*)(emis + (size_t)row * VV);
    int tid = threadIdx.x;
    __shared__ float sr[256];

    float m = -1e30f;
    for (int i = tid; i < VV / 4; i += 256) {
        float4 v = x4[i];
        m = fmaxf(m, fmaxf(fmaxf(v.x, v.y), fmaxf(v.z, v.w)));
    }
    sr[tid] = m; __syncthreads();
    for (int s = 128; s; s >>= 1) { if (tid < s) sr[tid] = fmaxf(sr[tid], sr[tid + s]); __syncthreads(); }
    m = sr[0]; __syncthreads();

    float sum = 0.f;
    for (int i = tid; i < VV / 4; i += 256) {
        float4 v = x4[i];
        sum += expf(v.x - m) + expf(v.y - m) + expf(v.z - m) + expf(v.w - m);
    }
    sr[tid] = sum; __syncthreads();
    for (int s = 128; s; s >>= 1) { if (tid < s) sr[tid] += sr[tid + s]; __syncthreads(); }
    if (tid == 0) g_lse[row] = m + logf(sr[0]);
}

// ---------------- kernel 2: transpose with lse subtract ----------------
__global__ void transpose_kernel(const float* __restrict__ emis) {
    __shared__ float tile[32][33];
    int s  = blockIdx.z;
    int v0 = blockIdx.x * 32;
    int h0 = blockIdx.y * 32;
    int tx = threadIdx.x, ty = threadIdx.y;

    #pragma unroll
    for (int r = 0; r < 4; ++r) {
        int h = h0 + ty + 8 * r;
        int v = v0 + tx;
        float val = 0.f;
        if (v < VV) val = emis[((size_t)s * HH + h) * VV + v] - g_lse[s * HH + h];
        tile[ty + 8 * r][tx] = val;
    }
    __syncthreads();
    #pragma unroll
    for (int r = 0; r < 4; ++r) {
        int v = v0 + ty + 8 * r;
        int h = h0 + tx;
        if (v < VV) g_leT[((size_t)s * VV + v) * HH + h] = tile[tx][ty + 8 * r];
    }
}

// ---------------- kernel 3: P8 = e5m2(softmax(tran)) + row-sum corr ----------------
__global__ void psoftmax_kernel(const float* __restrict__ tran) {
    int j = blockIdx.x;
    const float* row = tran + (size_t)j * HH;
    int tid = threadIdx.x;
    __shared__ float sr[256];

    float a = row[tid], b = row[tid + 256];
    sr[tid] = fmaxf(a, b); __syncthreads();
    for (int s = 128; s; s >>= 1) { if (tid < s) sr[tid] = fmaxf(sr[tid], sr[tid + s]); __syncthreads(); }
    float m = sr[0]; __syncthreads();

    float ea = expf(a - m), eb = expf(b - m);
    sr[tid] = ea + eb; __syncthreads();
    for (int s = 128; s; s >>= 1) { if (tid < s) sr[tid] += sr[tid + s]; __syncthreads(); }
    float inv = 1.0f / sr[0];          // NO x256 scale: PRMT dequant is exact value
    __syncthreads();

    __nv_fp8_storage_t qa = __nv_cvt_float_to_fp8(ea * inv, __NV_SATFINITE, __NV_E5M2);
    __nv_fp8_storage_t qb = __nv_cvt_float_to_fp8(eb * inv, __NV_SATFINITE, __NV_E5M2);
    g_P8[(size_t)j * HH + tid]       = qa;
    g_P8[(size_t)j * HH + tid + 256] = qb;

    __half_raw ha = __nv_cvt_fp8_to_halfraw(qa, __NV_E5M2);
    __half_raw hb = __nv_cvt_fp8_to_halfraw(qb, __NV_E5M2);
    float da = __half2float(*(__half*)&ha) + __half2float(*(__half*)&hb);
    sr[tid] = da; __syncthreads();
    for (int s = 128; s; s >>= 1) { if (tid < s) sr[tid] += sr[tid + s]; __syncthreads(); }
    if (tid == 0) g_corr[j] = 1.0f / sr[0];
}

// ---------------- kernel 4: gather em, smax & E ----------------
__global__ void emE_kernel(const void* __restrict__ obs_raw,
                           const float* __restrict__ priors) {
    int t = blockIdx.x, b = blockIdx.y;
    int tid = threadIdx.x;
    int lane = tid & 31, wid = tid >> 5;
    __shared__ float sm[4];

    int o[SS];
    if (g_is64) {
        const long long* p = (const long long*)obs_raw + ((size_t)(b * TT + t)) * SS;
        #pragma unroll
        for (int s = 0; s < SS; ++s) o[s] = (int)p[s];
    } else {
        const int* p = (const int*)obs_raw + ((size_t)(b * TT + t)) * SS;
        #pragma unroll
        for (int s = 0; s < SS; ++s) o[s] = p[s];
    }

    float4 acc = make_float4(0.f, 0.f, 0.f, 0.f);
    #pragma unroll
    for (int s = 0; s < SS; ++s) {
        const float4* r = (const float4*)(g_leT + ((size_t)s * VV + o[s]) * HH);
        float4 v = r[tid];
        acc.x += v.x; acc.y += v.y; acc.z += v.z; acc.w += v.w;
    }
    acc.x *= 0.25f; acc.y *= 0.25f; acc.z *= 0.25f; acc.w *= 0.25f;

    if (t == 0) {
        float4 pr = ((const float4*)priors)[tid];
        acc.x += pr.x; acc.y += pr.y; acc.z += pr.z; acc.w += pr.w;
    }

    float m = fmaxf(fmaxf(acc.x, acc.y), fmaxf(acc.z, acc.w));
    m = warp_max(m);
    if (lane == 0) sm[wid] = m;
    __syncthreads();
    m = fmaxf(fmaxf(sm[0], sm[1]), fmaxf(sm[2], sm[3]));

    float4 e;
    e.x = __expf(acc.x - m); e.y = __expf(acc.y - m);
    e.z = __expf(acc.z - m); e.w = __expf(acc.w - m);
    ((float4*)(g_E + ((size_t)(b * TT + t)) * HH))[tid] = e;
    if (tid == 0) g_smax[b * TT + t] = m;
}

// ---------------- kernel 5: forward, ROW-split cluster, PRMT dequant ----------------
// Identical protocol to R10; P is unscaled e5m2 -> dequant one PRMT per half2 pair.
// smem layout (bytes)
#define SM_P     0            // 256 rows x 512 e5m2 = 131072
#define SM_PART  131072       // 8 x 512 floats = 16384
#define SM_PH    147456       // 256 u32 (half2 bcast p, own j's) = 1024
#define SM_RECV  148480       // 2 x 256 floats (peer partials, double buffered) = 2048
#define SM_RED   150528       // 8 floats
#define SM_HP    150560       // 2 floats (peer H, double buffered)
#define SM_HPF   150568       // 1 float (peer final H) + pad
#define SM_MBAR  150576       // 8B (9 arrivals: 8 partial-warps + 1 H)
#define SM_MBARF 150584       // 8B (1 arrival: final H)
#define SMEM_TOTAL 150592

__global__ void __launch_bounds__(512, 1) __cluster_dims__(2, 1, 1)
forward_kernel(const void* __restrict__ lengths_raw, float* __restrict__ out) {
    extern __shared__ char sm[];
    const int tid  = threadIdx.x;
    const int b    = blockIdx.x >> 1;
    const unsigned rank = blockIdx.x & 1;
    const unsigned peer = rank ^ 1;
    const int lane = tid & 31, wid = tid >> 5;
    const bool own = ((unsigned)(tid >> 8) == rank);    // global state j = tid is mine
    const bool leader = (tid == (int)(rank << 8));
    const int u = tid & 255;

    const uint32_t sbase = smem_u32(sm);
    const uint32_t mbarV = sbase + SM_MBAR;
    const uint32_t mbarF = sbase + SM_MBARF;
    float*    part = (float*)(sm + SM_PART);
    unsigned* p_h  = (unsigned*)(sm + SM_PH);
    float*    recv = (float*)(sm + SM_RECV);
    float*    red  = (float*)(sm + SM_RED);
    float*    hps  = (float*)(sm + SM_HP);
    float*    hpf  = (float*)(sm + SM_HPF);

    if (tid == 0) { mbar_init(mbarV, 9); mbar_init(mbarF, 1); }

    // load own j-rows of P: rows [rank*256, +256), all 512 k (contiguous 128KB)
    {
        const uint4* src = (const uint4*)(g_P8 + (size_t)rank * HALFH * HH);
        uint4* dst = (uint4*)(sm + SM_P);
        #pragma unroll
        for (int r = 0; r < 16; ++r) dst[tid + 512 * r] = src[tid + 512 * r];
    }
    const float corrk = g_corr[tid];   // row-sum correction for row j = tid (own threads)
    __syncthreads();
    CLUSTER_SYNC_();

    const int len = g_is64 ? (int)((const long long*)lengths_raw)[b]
                           : ((const int*)lengths_raw)[b];
    const float* Eb  = g_E + (size_t)b * TT * HH;
    const float* smx = g_smax + (size_t)b * TT;

    unsigned pp = 0;
    float c = 0.f, run = 0.f;
    float R = 1.f;            // cross-half scale ratio (stale by 1 step; stable)
    float Ho = 1.f;           // own half-sum (register, all own threads)

    float e_cur = own ? __ldg(Eb + tid) : 0.f;
    float smt_cur = leader ? __ldg(smx) : 0.f;

    // matvec mapping: 8 groups x 64 threads; group g -> own-local j rows [g*32, g*32+32);
    // thread i owns global k = 8i..8i+7 via one LDS.64 (uint2) per j.
    const int g = tid >> 6, i = tid & 63;
    const uint2* P2  = (const uint2*)(sm + SM_P) + (size_t)(g * 32) * 64 + i;
    const uint4* ph4 = (const uint4*)(sm + SM_PH) + g * 8;
    float* prow = part + g * 512 + i * 8;

    for (int t = 0; t < len; ++t) {
        const int bufW = t & 1, bufR = bufW ^ 1;

        float e_next = 0.f, smt_next = 0.f;
        if (t + 1 < len) {
            if (own) e_next = __ldg(Eb + (size_t)(t + 1) * HH + tid);
            if (leader) smt_next = __ldg(smx + t + 1);
        }

        float w = 0.f;
        if (t == 0) {
            if (own) w = e_cur;
        } else {
            // matvec over own 256 j's (local p only), PRMT dequant
            unsigned prs[32];
            #pragma unroll
            for (int r = 0; r < 8; ++r) *(uint4*)&prs[4 * r] = ph4[r];
            __half2 a0 = __float2half2_rn(0.f), a1 = a0, a2 = a0, a3 = a0;
            #pragma unroll
            for (int jj = 0; jj < 32; ++jj) {
                uint2 q = P2[(size_t)jj * 64];
                __half2 hp = u32_h2(prs[jj]);
                a0 = __hfma2(hp, e5lo(q.x), a0);   // (k0,k2)
                a1 = __hfma2(hp, e5hi(q.x), a1);   // (k1,k3)
                a2 = __hfma2(hp, e5lo(q.y), a2);   // (k4,k6)
                a3 = __hfma2(hp, e5hi(q.y), a3);   // (k5,k7)
            }
            float2 f0 = __half22float2(a0), f1 = __half22float2(a1);
            float2 f2 = __half22float2(a2), f3 = __half22float2(a3);
            *(float4*)prow       = make_float4(f0.x, f1.x, f0.y, f1.y);
            *(float4*)(prow + 4) = make_float4(f2.x, f3.x, f2.y, f3.y);
            __syncthreads();

            // every thread reduces 8 partials for global k = tid
            float tot = 0.f;
            #pragma unroll
            for (int r = 0; r < 8; ++r) tot += part[r * 512 + tid];

            if (!own) {
                // ship peer's k-half; ONE aggregated arrive per warp
                st_remote_f32(sbase + SM_RECV + ((unsigned)bufW << 10) + 4u * (unsigned)u, peer, tot);
                __syncwarp();
                if (lane == 0) mbar_arrive_remote(mbarV, peer);
            } else {
                // wait: peer partial-warps (this step) + peer H_{t-1}
                mbar_wait(mbarV, pp); pp ^= 1;
                float Hp = hps[bufR];                 // peer H_{t-1}
                R = R * Hp * __frcp_rn(Ho);           // Ho still holds H_{t-1}
                float v = fmaf(R, recv[bufW * 256 + u], tot);
                w = e_cur * v;
            }
        }

        if (own) {
            float s1 = warp_sum(w);
            if (lane == 0) red[wid & 7] = s1;
            asm volatile("bar.sync 1, 256;" ::: "memory");
            float Hn = red[0] + red[1] + red[2] + red[3] + red[4] + red[5] + red[6] + red[7];

            // normalize own half by 2*Hn (current -> stable); corr fixes quant row sums
            float pk = w * __frcp_rn(Hn + Hn) * corrk;
            unsigned hu = (unsigned)__half_as_ushort(__float2half_rn(pk));
            hu |= hu << 16;
            p_h[u] = hu;
            Ho = Hn;

            if (leader) {
                if (t < len - 1) {
                    st_remote_f32(sbase + SM_HP + 4u * (unsigned)bufW, peer, Ho);
                    mbar_arrive_remote(mbarV, peer);
                } else {
                    st_remote_f32(sbase + SM_HPF, peer, Ho);
                    mbar_arrive_remote(mbarF, peer);
                }
                c += smt_cur;
                run += __logf(Ho + Ho);
            }
        }
        e_cur = e_next; smt_cur = smt_next;
        __syncthreads();
    }

    if (leader && rank == 0) {
        mbar_wait(mbarF, 0);
        // run includes log(2 Ho_L); replace with log(Ho_L + R*Hp_L)
        out[b] = c + run - __logf(Ho + Ho) + __logf(fmaf(R, hpf[0], Ho));
    }
    CLUSTER_SYNC_();
}

// ---------------- launcher ----------------
extern "C" void kernel_launch(void* const* d_in, const int* in_sizes, int n_in,
                              void* d_out, int out_size) {
    const void*  obs     = d_in[0];
    const void*  lengths = d_in[1];
    const float* emis    = (const float*)d_in[2];
    const float* tran    = (const float*)d_in[3];
    const float* priors  = (const float*)d_in[4];
    float* out = (float*)d_out;

    cudaFuncSetAttribute(forward_kernel, cudaFuncAttributeMaxDynamicSharedMemorySize, SMEM_TOTAL);

    detect_kernel<<<1, 32>>>((const int*)obs);
    lse_kernel<<<SS * HH, 256>>>(emis);
    transpose_kernel<<<dim3((VV + 31) / 32, HH / 32, SS), dim3(32, 8)>>>(emis);
    psoftmax_kernel<<<HH, 256>>>(tran);
    emE_kernel<<<dim3(TT, BB), 128>>>(obs, priors);
    forward_kernel<<<BB * 2, 512, SMEM_TOTAL>>>(lengths, out);
}

// round 13
// speedup vs baseline: 1.7779x; 1.0534x over previous
#include <cuda_runtime.h>
#include <cuda_bf16.h>
#include <cuda_fp16.h>
#include <cuda_fp8.h>
#include <cstdint>

#define BB 64
#define TT 512
#define SS 4
#define HH 512
#define VV 10000
#define HALFH 256

// ---------------- device scratch ----------------
__device__ float g_lse[SS * HH];
__device__ float g_leT[(size_t)SS * VV * HH];          // [s][v][h]
__device__ float g_E[(size_t)BB * TT * HH];            // exp(em - smax)
__device__ float g_smax[BB * TT];
__device__ unsigned char g_P8[HH * HH];                // e5m2(P), row-major [j][k] (NO scale)
__device__ float g_corr[HH];                           // per-row quant row-sum correction
__device__ int g_is64;

// ---------------- helpers ----------------
__device__ __forceinline__ float warp_sum(float v) {
    #pragma unroll
    for (int o = 16; o; o >>= 1) v += __shfl_xor_sync(0xffffffffu, v, o);
    return v;
}
__device__ __forceinline__ float warp_max(float v) {
    #pragma unroll
    for (int o = 16; o; o >>= 1) v = fmaxf(v, __shfl_xor_sync(0xffffffffu, v, o));
    return v;
}
__device__ __forceinline__ uint32_t smem_u32(const void* p) {
    uint32_t a;
    asm("{ .reg .u64 t; cvta.to.shared.u64 t, %1; cvt.u32.u64 %0, t; }" : "=r"(a) : "l"(p));
    return a;
}
__device__ __forceinline__ __half2 u32_h2(unsigned u) {
    __half2 h;
    *reinterpret_cast<unsigned*>(&h) = u;
    return h;
}
// e5m2 IS the top byte of fp16: dequant = ONE PRMT per half2 pair, value EXACT.
__device__ __forceinline__ __half2 e5lo(unsigned q) { return u32_h2(__byte_perm(q, 0, 0x2404)); }  // (b0,b2)
__device__ __forceinline__ __half2 e5hi(unsigned q) { return u32_h2(__byte_perm(q, 0, 0x3414)); }  // (b1,b3)

__device__ __forceinline__ void mbar_init(uint32_t m, unsigned cnt) {
    asm volatile("mbarrier.init.shared.b64 [%0], %1;" :: "r"(m), "r"(cnt) : "memory");
}
__device__ __forceinline__ void mbar_arrive_remote(uint32_t m_local, unsigned peer) {
    asm volatile("{\n\t.reg .b32 r;\n\t"
                 "mapa.shared::cluster.u32 r, %0, %1;\n\t"
                 "mbarrier.arrive.release.cluster.shared::cluster.b64 _, [r];\n\t}"
                 :: "r"(m_local), "r"(peer) : "memory");
}
__device__ __forceinline__ void st_remote_f32(uint32_t a_local, unsigned peer, float v) {
    asm volatile("{\n\t.reg .b32 r;\n\t"
                 "mapa.shared::cluster.u32 r, %0, %1;\n\t"
                 "st.shared::cluster.f32 [r], %2;\n\t}"
                 :: "r"(a_local), "r"(peer), "f"(v) : "memory");
}
__device__ __forceinline__ void mbar_wait(uint32_t m, unsigned parity) {
    asm volatile("{\n\t.reg .pred P;\n\t"
                 "WL_%=:\n\t"
                 "mbarrier.try_wait.parity.acquire.cluster.shared::cta.b64 P, [%0], %1, 0x989680;\n\t"
                 "@P bra WD_%=;\n\t"
                 "bra WL_%=;\n\t"
                 "WD_%=:\n\t}"
                 :: "r"(m), "r"(parity) : "memory");
}
#define CLUSTER_SYNC_() do { \
    asm volatile("barrier.cluster.arrive.aligned;" ::: "memory"); \
    asm volatile("barrier.cluster.wait.aligned;" ::: "memory"); } while (0)

// ---------------- kernel 0: detect int64 vs int32 ----------------
__global__ void detect_kernel(const int* obs32) {
    if (threadIdx.x == 0) {
        int f = 1;
        for (int i = 0; i < 128; ++i)
            if (obs32[2 * i + 1] != 0) { f = 0; break; }
        g_is64 = f;
    }
}

// ---------------- kernel 1: lse over V ----------------
__global__ void lse_kernel(const float* __restrict__ emis) {
    int row = blockIdx.x;
    const float4* x4 = (const float4*)(emis + (size_t)row * VV);
    int tid = threadIdx.x;
    __shared__ float sr[256];

    float m = -1e30f;
    for (int i = tid; i < VV / 4; i += 256) {
        float4 v = x4[i];
        m = fmaxf(m, fmaxf(fmaxf(v.x, v.y), fmaxf(v.z, v.w)));
    }
    sr[tid] = m; __syncthreads();
    for (int s = 128; s; s >>= 1) { if (tid < s) sr[tid] = fmaxf(sr[tid], sr[tid + s]); __syncthreads(); }
    m = sr[0]; __syncthreads();

    float sum = 0.f;
    for (int i = tid; i < VV / 4; i += 256) {
        float4 v = x4[i];
        sum += expf(v.x - m) + expf(v.y - m) + expf(v.z - m) + expf(v.w - m);
    }
    sr[tid] = sum; __syncthreads();
    for (int s = 128; s; s >>= 1) { if (tid < s) sr[tid] += sr[tid + s]; __syncthreads(); }
    if (tid == 0) g_lse[row] = m + logf(sr[0]);
}

// ---------------- kernel 2: transpose with lse subtract ----------------
__global__ void transpose_kernel(const float* __restrict__ emis) {
    __shared__ float tile[32][33];
    int s  = blockIdx.z;
    int v0 = blockIdx.x * 32;
    int h0 = blockIdx.y * 32;
    int tx = threadIdx.x, ty = threadIdx.y;

    #pragma unroll
    for (int r = 0; r < 4; ++r) {
        int h = h0 + ty + 8 * r;
        int v = v0 + tx;
        float val = 0.f;
        if (v < VV) val = emis[((size_t)s * HH + h) * VV + v] - g_lse[s * HH + h];
        tile[ty + 8 * r][tx] = val;
    }
    __syncthreads();
    #pragma unroll
    for (int r = 0; r < 4; ++r) {
        int v = v0 + ty + 8 * r;
        int h = h0 + tx;
        if (v < VV) g_leT[((size_t)s * VV + v) * HH + h] = tile[tx][ty + 8 * r];
    }
}

// ---------------- kernel 3: P8 = e5m2(softmax(tran)) + row-sum corr ----------------
__global__ void psoftmax_kernel(const float* __restrict__ tran) {
    int j = blockIdx.x;
    const float* row = tran + (size_t)j * HH;
    int tid = threadIdx.x;
    __shared__ float sr[256];

    float a = row[tid], b = row[tid + 256];
    sr[tid] = fmaxf(a, b); __syncthreads();
    for (int s = 128; s; s >>= 1) { if (tid < s) sr[tid] = fmaxf(sr[tid], sr[tid + s]); __syncthreads(); }
    float m = sr[0]; __syncthreads();

    float ea = expf(a - m), eb = expf(b - m);
    sr[tid] = ea + eb; __syncthreads();
    for (int s = 128; s; s >>= 1) { if (tid < s) sr[tid] += sr[tid + s]; __syncthreads(); }
    float inv = 1.0f / sr[0];          // unscaled: PRMT dequant is the exact value
    __syncthreads();

    __nv_fp8_storage_t qa = __nv_cvt_float_to_fp8(ea * inv, __NV_SATFINITE, __NV_E5M2);
    __nv_fp8_storage_t qb = __nv_cvt_float_to_fp8(eb * inv, __NV_SATFINITE, __NV_E5M2);
    g_P8[(size_t)j * HH + tid]       = qa;
    g_P8[(size_t)j * HH + tid + 256] = qb;

    __half_raw ha = __nv_cvt_fp8_to_halfraw(qa, __NV_E5M2);
    __half_raw hb = __nv_cvt_fp8_to_halfraw(qb, __NV_E5M2);
    float da = __half2float(*(__half*)&ha) + __half2float(*(__half*)&hb);
    sr[tid] = da; __syncthreads();
    for (int s = 128; s; s >>= 1) { if (tid < s) sr[tid] += sr[tid + s]; __syncthreads(); }
    if (tid == 0) g_corr[j] = 1.0f / sr[0];
}

// ---------------- kernel 4: gather em, smax & E ----------------
__global__ void emE_kernel(const void* __restrict__ obs_raw,
                           const float* __restrict__ priors) {
    int t = blockIdx.x, b = blockIdx.y;
    int tid = threadIdx.x;
    int lane = tid & 31, wid = tid >> 5;
    __shared__ float sm[4];

    int o[SS];
    if (g_is64) {
        const long long* p = (const long long*)obs_raw + ((size_t)(b * TT + t)) * SS;
        #pragma unroll
        for (int s = 0; s < SS; ++s) o[s] = (int)p[s];
    } else {
        const int* p = (const int*)obs_raw + ((size_t)(b * TT + t)) * SS;
        #pragma unroll
        for (int s = 0; s < SS; ++s) o[s] = p[s];
    }

    float4 acc = make_float4(0.f, 0.f, 0.f, 0.f);
    #pragma unroll
    for (int s = 0; s < SS; ++s) {
        const float4* r = (const float4*)(g_leT + ((size_t)s * VV + o[s]) * HH);
        float4 v = r[tid];
        acc.x += v.x; acc.y += v.y; acc.z += v.z; acc.w += v.w;
    }
    acc.x *= 0.25f; acc.y *= 0.25f; acc.z *= 0.25f; acc.w *= 0.25f;

    if (t == 0) {
        float4 pr = ((const float4*)priors)[tid];
        acc.x += pr.x; acc.y += pr.y; acc.z += pr.z; acc.w += pr.w;
    }

    float m = fmaxf(fmaxf(acc.x, acc.y), fmaxf(acc.z, acc.w));
    m = warp_max(m);
    if (lane == 0) sm[wid] = m;
    __syncthreads();
    m = fmaxf(fmaxf(sm[0], sm[1]), fmaxf(sm[2], sm[3]));

    float4 e;
    e.x = __expf(acc.x - m); e.y = __expf(acc.y - m);
    e.z = __expf(acc.z - m); e.w = __expf(acc.w - m);
    ((float4*)(g_E + ((size_t)(b * TT + t)) * HH))[tid] = e;
    if (tid == 0) g_smax[b * TT + t] = m;
}

// ---------------- kernel 5: forward, ROW-split cluster, half-register P ----------------
// R12 protocol; j-rows 16..31 of each thread's group held in REGISTERS (32 regs),
// halving smem crossbar traffic for P (1024 -> 512 cyc/step).
// smem layout (bytes)
#define SM_P     0            // 256 rows x 512 e5m2 = 131072
#define SM_PART  131072       // 8 x 512 floats = 16384
#define SM_PH    147456       // 256 u32 (half2 bcast p, own j's) = 1024
#define SM_RECV  148480       // 2 x 256 floats (peer partials, double buffered) = 2048
#define SM_RED   150528       // 8 floats
#define SM_HP    150560       // 2 floats (peer H, double buffered)
#define SM_HPF   150568       // 1 float (peer final H) + pad
#define SM_MBAR  150576       // 8B (9 arrivals: 8 partial-warps + 1 H)
#define SM_MBARF 150584       // 8B (1 arrival: final H)
#define SMEM_TOTAL 150592

__global__ void __launch_bounds__(512, 1) __cluster_dims__(2, 1, 1)
forward_kernel(const void* __restrict__ lengths_raw, float* __restrict__ out) {
    extern __shared__ char sm[];
    const int tid  = threadIdx.x;
    const int b    = blockIdx.x >> 1;
    const unsigned rank = blockIdx.x & 1;
    const unsigned peer = rank ^ 1;
    const int lane = tid & 31, wid = tid >> 5;
    const bool own = ((unsigned)(tid >> 8) == rank);    // global state j = tid is mine
    const bool leader = (tid == (int)(rank << 8));
    const int u = tid & 255;

    const uint32_t sbase = smem_u32(sm);
    const uint32_t mbarV = sbase + SM_MBAR;
    const uint32_t mbarF = sbase + SM_MBARF;
    float*    part = (float*)(sm + SM_PART);
    unsigned* p_h  = (unsigned*)(sm + SM_PH);
    float*    recv = (float*)(sm + SM_RECV);
    float*    red  = (float*)(sm + SM_RED);
    float*    hps  = (float*)(sm + SM_HP);
    float*    hpf  = (float*)(sm + SM_HPF);

    if (tid == 0) { mbar_init(mbarV, 9); mbar_init(mbarF, 1); }

    // load own j-rows of P: rows [rank*256, +256), all 512 k (contiguous 128KB)
    {
        const uint4* src = (const uint4*)(g_P8 + (size_t)rank * HALFH * HH);
        uint4* dst = (uint4*)(sm + SM_P);
        #pragma unroll
        for (int r = 0; r < 16; ++r) dst[tid + 512 * r] = src[tid + 512 * r];
    }
    const float corrk = g_corr[tid];   // row-sum correction for row j = tid (own threads)
    __syncthreads();
    CLUSTER_SYNC_();

    // matvec mapping: 8 groups x 64 threads; group g -> own-local j rows [g*32, g*32+32);
    // thread i owns global k = 8i..8i+7 via one uint2 per j.
    const int g = tid >> 6, i = tid & 63;
    const uint2* P2  = (const uint2*)(sm + SM_P) + (size_t)(g * 32) * 64 + i;
    const uint4* ph4 = (const uint4*)(sm + SM_PH) + g * 8;
    float* prow = part + g * 512 + i * 8;

    // register-resident P: this thread's j-rows 16..31 (32 regs)
    uint2 Pr[16];
    #pragma unroll
    for (int r = 0; r < 16; ++r) Pr[r] = P2[(size_t)(16 + r) * 64];

    const int len = g_is64 ? (int)((const long long*)lengths_raw)[b]
                           : ((const int*)lengths_raw)[b];
    const float* Eb  = g_E + (size_t)b * TT * HH;
    const float* smx = g_smax + (size_t)b * TT;

    unsigned pp = 0;
    float c = 0.f, run = 0.f;
    float R = 1.f;            // cross-half scale ratio (stale by 1 step; stable)
    float Ho = 1.f;           // own half-sum (register, all own threads)

    float e_cur = own ? __ldg(Eb + tid) : 0.f;
    float smt_cur = leader ? __ldg(smx) : 0.f;

    for (int t = 0; t < len; ++t) {
        const int bufW = t & 1, bufR = bufW ^ 1;

        float e_next = 0.f, smt_next = 0.f;
        if (t + 1 < len) {
            if (own) e_next = __ldg(Eb + (size_t)(t + 1) * HH + tid);
            if (leader) smt_next = __ldg(smx + t + 1);
        }

        float w = 0.f;
        if (t == 0) {
            if (own) w = e_cur;
        } else {
            // matvec over own 256 j's: jj 0..15 from smem, jj 16..31 from registers
            __half2 a0 = __float2half2_rn(0.f), a1 = a0, a2 = a0, a3 = a0;
            {
                unsigned prs[16];
                #pragma unroll
                for (int r = 0; r < 4; ++r) *(uint4*)&prs[4 * r] = ph4[r];
                #pragma unroll
                for (int jj = 0; jj < 16; ++jj) {
                    uint2 q = P2[(size_t)jj * 64];
                    __half2 hp = u32_h2(prs[jj]);
                    a0 = __hfma2(hp, e5lo(q.x), a0);
                    a1 = __hfma2(hp, e5hi(q.x), a1);
                    a2 = __hfma2(hp, e5lo(q.y), a2);
                    a3 = __hfma2(hp, e5hi(q.y), a3);
                }
            }
            {
                unsigned prs[16];
                #pragma unroll
                for (int r = 0; r < 4; ++r) *(uint4*)&prs[4 * r] = ph4[4 + r];
                #pragma unroll
                for (int jj = 0; jj < 16; ++jj) {
                    uint2 q = Pr[jj];
                    __half2 hp = u32_h2(prs[jj]);
                    a0 = __hfma2(hp, e5lo(q.x), a0);
                    a1 = __hfma2(hp, e5hi(q.x), a1);
                    a2 = __hfma2(hp, e5lo(q.y), a2);
                    a3 = __hfma2(hp, e5hi(q.y), a3);
                }
            }
            float2 f0 = __half22float2(a0), f1 = __half22float2(a1);
            float2 f2 = __half22float2(a2), f3 = __half22float2(a3);
            *(float4*)prow       = make_float4(f0.x, f1.x, f0.y, f1.y);
            *(float4*)(prow + 4) = make_float4(f2.x, f3.x, f2.y, f3.y);
            __syncthreads();

            // every thread reduces 8 partials for global k = tid
            float tot = 0.f;
            #pragma unroll
            for (int r = 0; r < 8; ++r) tot += part[r * 512 + tid];

            if (!own) {
                // ship peer's k-half; ONE aggregated arrive per warp
                st_remote_f32(sbase + SM_RECV + ((unsigned)bufW << 10) + 4u * (unsigned)u, peer, tot);
                __syncwarp();
                if (lane == 0) mbar_arrive_remote(mbarV, peer);
            } else {
                // wait: peer partial-warps (this step) + peer H_{t-1}
                mbar_wait(mbarV, pp); pp ^= 1;
                float Hp = hps[bufR];                 // peer H_{t-1}
                R = R * Hp * __frcp_rn(Ho);           // Ho still holds H_{t-1}
                float v = fmaf(R, recv[bufW * 256 + u], tot);
                w = e_cur * v;
            }
        }

        if (own) {
            float s1 = warp_sum(w);
            if (lane == 0) red[wid & 7] = s1;
            asm volatile("bar.sync 1, 256;" ::: "memory");
            float Hn = red[0] + red[1] + red[2] + red[3] + red[4] + red[5] + red[6] + red[7];

            // normalize own half by 2*Hn (current -> stable); corr fixes quant row sums
            float pk = w * __frcp_rn(Hn + Hn) * corrk;
            unsigned hu = (unsigned)__half_as_ushort(__float2half_rn(pk));
            hu |= hu << 16;
            p_h[u] = hu;
            Ho = Hn;

            if (leader) {
                if (t < len - 1) {
                    st_remote_f32(sbase + SM_HP + 4u * (unsigned)bufW, peer, Ho);
                    mbar_arrive_remote(mbarV, peer);
                } else {
                    st_remote_f32(sbase + SM_HPF, peer, Ho);
                    mbar_arrive_remote(mbarF, peer);
                }
                c += smt_cur;
                run += __logf(Ho + Ho);
            }
        }
        e_cur = e_next; smt_cur = smt_next;
        __syncthreads();
    }

    if (leader && rank == 0) {
        mbar_wait(mbarF, 0);
        // run includes log(2 Ho_L); replace with log(Ho_L + R*Hp_L)
        out[b] = c + run - __logf(Ho + Ho) + __logf(fmaf(R, hpf[0], Ho));
    }
    CLUSTER_SYNC_();
}

// ---------------- launcher ----------------
extern "C" void kernel_launch(void* const* d_in, const int* in_sizes, int n_in,
                              void* d_out, int out_size) {
    const void*  obs     = d_in[0];
    const void*  lengths = d_in[1];
    const float* emis    = (const float*)d_in[2];
    const float* tran    = (const float*)d_in[3];
    const float* priors  = (const float*)d_in[4];
    float* out = (float*)d_out;

    cudaFuncSetAttribute(forward_kernel, cudaFuncAttributeMaxDynamicSharedMemorySize, SMEM_TOTAL);

    detect_kernel<<<1, 32>>>((const int*)obs);
    lse_kernel<<<SS * HH, 256>>>(emis);
    transpose_kernel<<<dim3((VV + 31) / 32, HH / 32, SS), dim3(32, 8)>>>(emis);
    psoftmax_kernel<<<HH, 256>>>(tran);
    emE_kernel<<<dim3(TT, BB), 128>>>(obs, priors);
    forward_kernel<<<BB * 2, 512, SMEM_TOTAL>>>(lengths, out);
}